// round 16
// baseline (speedup 1.0000x reference)
#include <cuda_runtime.h>
#include <cuda_bf16.h>
#include <cstdint>

#define Bx   16
#define Nn   1024
#define DINc 128
#define Hh   4
#define Dd   32
#define HD   128
#define BN   (Bx*Nn)
#define LOG2E 1.4426950408889634f

// ---------------------------------------------------------------------------
// Scratch (device globals — no allocation allowed in kernel_launch)
// ---------------------------------------------------------------------------
__device__ float    g_hT[(size_t)Bx*Hh*Nn*Dd];   // 8.4 MB tf32-rounded, [b][hh][j][d]
__device__ float    g_Ei[(size_t)Hh*BN];         // exp2(ei)      [hh][row]
__device__ float    g_Fi[(size_t)Hh*BN];         // exp2(0.2 ei)
__device__ float    g_Ej[(size_t)Hh*BN];
__device__ float    g_Fj[(size_t)Hh*BN];
__device__ unsigned g_am[(size_t)32*BN];         // [jt][row] packed adjacency bits

__device__ __forceinline__ float tf32r(float x) {
    uint32_t u; asm("cvt.rna.tf32.f32 %0, %1;" : "=r"(u) : "f"(x));
    return __uint_as_float(u);
}
__device__ __forceinline__ float ex2(float x) {
    float p; asm("ex2.approx.ftz.f32 %0, %1;" : "=f"(p) : "f"(x));
    return p;
}

#define MMA_TF32(c0,c1,c2,c3, A0,A1,A2,A3, B0,B1) \
    asm("mma.sync.aligned.m16n8k8.row.col.f32.tf32.tf32.f32 " \
        "{%0,%1,%2,%3}, {%4,%5,%6,%7}, {%8,%9}, {%0,%1,%2,%3};" \
        : "+f"(c0), "+f"(c1), "+f"(c2), "+f"(c3) \
        : "r"(A0), "r"(A1), "r"(A2), "r"(A3), "r"(B0), "r"(B1))

// ---------------------------------------------------------------------------
// Kernel 1 (fused): h = x@W + b via 3xTF32 mma.sync  ->  g_hT,
// edge logits from accumulator fragments -> g_Ei/Fi/Ej/Fj,
// adjacency bit-packing -> g_am.
// NEW: L2 prefetch of the block's adj slice BEFORE the GEMM mainloop, so
// the 128 KB DRAM fetch overlaps compute and the pack phase hits L2.
// ---------------------------------------------------------------------------
__global__ void __launch_bounds__(256, 2) k_gemm(const float* __restrict__ x,
                                                 const float* __restrict__ W,
                                                 const float* __restrict__ bias,
                                                 const float* __restrict__ a,
                                                 const int* __restrict__ adj) {
    __shared__ __align__(16) float xs[32*132];
    __shared__ float as[64];
    const int tid  = threadIdx.x;
    const int lane = tid & 31;
    const int w    = tid >> 5;
    const int qid  = lane >> 2;
    const int tq   = lane & 3;
    const int m0   = (w & 1) * 16;
    const int hh   = w >> 1;
    const int n0   = hh * 32;
    const size_t row0 = (size_t)blockIdx.x * 32;

    for (int i = tid; i < 32*32; i += 256) {
        const int r = i >> 5, c4 = i & 31;
        float4 v = ((const float4*)(x + (row0 + r)*DINc))[c4];
        *(float4*)&xs[r*132 + c4*4] = v;
    }
    if (tid < 64) as[tid] = a[tid];

    // L2 prefetch of this block's 128 KB adj slice (1024 lines, 4/thread)
    {
        const char* abase = (const char*)(adj + row0*Nn);
#pragma unroll
        for (int q = 0; q < 4; q++)
            asm volatile("prefetch.global.L2 [%0];" :: "l"(abase + (size_t)(tid + q*256)*128));
    }
    __syncthreads();

    float acc[4][4];
#pragma unroll
    for (int nt = 0; nt < 4; nt++)
#pragma unroll
        for (int k = 0; k < 4; k++) acc[nt][k] = 0.f;

#pragma unroll
    for (int ks = 0; ks < 16; ks++) {
        const int k0 = ks*8;
        float wv0[4], wv1[4];
        const float* Wk = W + (size_t)(k0 + tq)*HD + n0 + qid;
#pragma unroll
        for (int nt = 0; nt < 4; nt++) wv0[nt] = __ldg(Wk + nt*8);
#pragma unroll
        for (int nt = 0; nt < 4; nt++) wv1[nt] = __ldg(Wk + 4*HD + nt*8);

        const float av0 = xs[(m0+qid  )*132 + k0 + tq];
        const float av1 = xs[(m0+qid+8)*132 + k0 + tq];
        const float av2 = xs[(m0+qid  )*132 + k0 + tq + 4];
        const float av3 = xs[(m0+qid+8)*132 + k0 + tq + 4];
        const float ah0 = tf32r(av0), ah1 = tf32r(av1), ah2 = tf32r(av2), ah3 = tf32r(av3);
        const uint32_t Ah0 = __float_as_uint(ah0), Ah1 = __float_as_uint(ah1);
        const uint32_t Ah2 = __float_as_uint(ah2), Ah3 = __float_as_uint(ah3);
        const uint32_t Al0 = __float_as_uint(av0 - ah0), Al1 = __float_as_uint(av1 - ah1);
        const uint32_t Al2 = __float_as_uint(av2 - ah2), Al3 = __float_as_uint(av3 - ah3);

#pragma unroll
        for (int nt = 0; nt < 4; nt++) {
            const float bh0 = tf32r(wv0[nt]), bh1 = tf32r(wv1[nt]);
            const uint32_t Bh0 = __float_as_uint(bh0), Bh1 = __float_as_uint(bh1);
            const uint32_t Bl0 = __float_as_uint(wv0[nt] - bh0);
            const uint32_t Bl1 = __float_as_uint(wv1[nt] - bh1);
            MMA_TF32(acc[nt][0], acc[nt][1], acc[nt][2], acc[nt][3],
                     Ah0, Ah1, Ah2, Ah3, Bl0, Bl1);
            MMA_TF32(acc[nt][0], acc[nt][1], acc[nt][2], acc[nt][3],
                     Al0, Al1, Al2, Al3, Bh0, Bh1);
            MMA_TF32(acc[nt][0], acc[nt][1], acc[nt][2], acc[nt][3],
                     Ah0, Ah1, Ah2, Ah3, Bh0, Bh1);
        }
    }

    const int b  = (int)(row0 >> 10);
    const int jt = (int)((row0 >> 5) & 31);
    float* htb = g_hT + (((size_t)b*Hh + hh) << 15) + ((size_t)jt*32 << 5);

    float si0 = 0.f, si1 = 0.f, sj0 = 0.f, sj1 = 0.f;
#pragma unroll
    for (int nt = 0; nt < 4; nt++) {
        const int d0 = nt*8 + 2*tq;
        const float bc0 = __ldg(&bias[n0 + d0]), bc1 = __ldg(&bias[n0 + d0 + 1]);
        const float h00 = acc[nt][0] + bc0, h01 = acc[nt][1] + bc1;
        const float h10 = acc[nt][2] + bc0, h11 = acc[nt][3] + bc1;
        const float ai0 = as[d0], ai1 = as[d0 + 1];
        const float aj0 = as[32 + d0], aj1 = as[32 + d0 + 1];
        si0 = fmaf(h00, ai0, fmaf(h01, ai1, si0));
        si1 = fmaf(h10, ai0, fmaf(h11, ai1, si1));
        sj0 = fmaf(h00, aj0, fmaf(h01, aj1, sj0));
        sj1 = fmaf(h10, aj0, fmaf(h11, aj1, sj1));
        float2 v0 = { tf32r(h00), tf32r(h01) };
        float2 v1 = { tf32r(h10), tf32r(h11) };
        *(float2*)(htb + (size_t)(m0 + qid    )*32 + d0) = v0;
        *(float2*)(htb + (size_t)(m0 + qid + 8)*32 + d0) = v1;
    }
#pragma unroll
    for (int o = 1; o <= 2; o <<= 1) {
        si0 += __shfl_xor_sync(0xffffffffu, si0, o);
        si1 += __shfl_xor_sync(0xffffffffu, si1, o);
        sj0 += __shfl_xor_sync(0xffffffffu, sj0, o);
        sj1 += __shfl_xor_sync(0xffffffffu, sj1, o);
    }
    if (tq == 0) {
        const size_t r0g = (size_t)hh*BN + row0 + m0 + qid;
        const float e0 = si0*LOG2E, e1 = si1*LOG2E;
        const float f0 = sj0*LOG2E, f1 = sj1*LOG2E;
        g_Ei[r0g]     = ex2(e0);      g_Ei[r0g + 8] = ex2(e1);
        g_Fi[r0g]     = ex2(0.2f*e0); g_Fi[r0g + 8] = ex2(0.2f*e1);
        g_Ej[r0g]     = ex2(f0);      g_Ej[r0g + 8] = ex2(f1);
        g_Fj[r0g]     = ex2(0.2f*f0); g_Fj[r0g + 8] = ex2(0.2f*f1);
    }

    // ---- adjacency pack: batched loads (now L2 hits), shfl-or reduction
#pragma unroll
    for (int rr = 0; rr < 4; rr++) {
        const size_t row = row0 + w*4 + rr;
        const int4* arow = (const int4*)(adj + row*Nn);
        int4 v[8];
#pragma unroll
        for (int c = 0; c < 8; c++) v[c] = __ldg(&arow[c*32 + lane]);
#pragma unroll
        for (int c = 0; c < 8; c++) {
            unsigned nib = (unsigned)(v[c].x > 0) | ((unsigned)(v[c].y > 0) << 1)
                         | ((unsigned)(v[c].z > 0) << 2) | ((unsigned)(v[c].w > 0) << 3);
            nib <<= (lane & 7)*4;
            nib |= __shfl_xor_sync(0xffffffffu, nib, 1);
            nib |= __shfl_xor_sync(0xffffffffu, nib, 2);
            nib |= __shfl_xor_sync(0xffffffffu, nib, 4);
            if ((lane & 7) == 0)
                g_am[(size_t)(c*4 + (lane >> 3))*BN + row] = nib;
        }
    }
}

// ---------------------------------------------------------------------------
// Kernel 2: flash attention via mma.sync tf32 (unsplit, occupancy-fixed).
// Grid (8, Hh, Bx) = 512 blocks, 256 thr = 8 warps, warp owns 16 i-rows
// (block = 128 rows, all 32 j-tiles). Block-shared double-buffered h tile
// (1 float4/thread/tile), one __syncthreads per j-tile. launch_bounds(256,3)
// -> 85-reg budget -> 24 warps/SM. Direct normalized write to out.
// ---------------------------------------------------------------------------
__global__ void __launch_bounds__(256, 3) k_attn(float* __restrict__ out) {
    __shared__ float EjS[Nn], FjS[Nn];     // 8 KB, permuted
    __shared__ float hs[2][32*40];         // 10.2 KB double-buffered h tile

    const int tid  = threadIdx.x;
    const int lane = tid & 31;
    const int w    = tid >> 5;             // warp 0..7, rows w*16..w*16+15
    const int qid  = lane >> 2;
    const int tq   = lane & 3;
    const int hh   = blockIdx.y;
    const int b    = blockIdx.z;
    const int i0   = blockIdx.x * 128;
    const size_t bN = (size_t)b * Nn;

    // stage Ej/Fj permuted: within each 32-group, j = tq + 4t -> pos = tq*8 + t
    {
        const float* Ejsrc = g_Ej + (size_t)hh*BN + bN;
        const float* Fjsrc = g_Fj + (size_t)hh*BN + bN;
        for (int k = tid; k < Nn; k += 256) {
            const int pos = (k & ~31) | (((k & 3) << 3) | ((k >> 2) & 7));
            EjS[pos] = Ejsrc[k];
            FjS[pos] = Fjsrc[k];
        }
    }

    float Eir[2], Fir[2], lden[2];
#pragma unroll
    for (int m = 0; m < 2; m++) {
        const size_t o = (size_t)hh*BN + bN + i0 + w*16 + qid + 8*m;
        Eir[m] = __ldg(&g_Ei[o]);
        Fir[m] = __ldg(&g_Fi[o]);
        lden[m] = 0.f;
    }

    float acc[4][4];
#pragma unroll
    for (int nt = 0; nt < 4; nt++)
#pragma unroll
        for (int k = 0; k < 4; k++) acc[nt][k] = 0.f;

    const float* htsrc = g_hT + (((size_t)b*Hh + hh) << 15);
    const unsigned* amp = g_am + bN + i0 + w*16 + qid;

    // prologue: stage tile 0 (1 float4 per thread)
    const int sr = (tid >> 3)*40 + (tid & 7)*4;
    float4 r0 = ((const float4*)htsrc)[tid];
    __syncthreads();                        // EjS/FjS visible
    *(float4*)&hs[0][sr] = r0;
    __syncthreads();

    for (int lt = 0; lt < 32; lt++) {
        const int buf = lt & 1;
        if (lt < 31)
            r0 = ((const float4*)(htsrc + (size_t)(lt + 1)*1024))[tid];

        unsigned mb[2];
#pragma unroll
        for (int m = 0; m < 2; m++)
            mb[m] = __ldg(amp + (size_t)lt*BN + 8*m) >> tq;

        // ---- phase A: P in A-fragment registers (no MUFU)
        float ejt[8], fjt[8];
        *(float4*)&ejt[0] = *(const float4*)&EjS[lt*32 + tq*8];
        *(float4*)&ejt[4] = *(const float4*)&EjS[lt*32 + tq*8 + 4];
        *(float4*)&fjt[0] = *(const float4*)&FjS[lt*32 + tq*8];
        *(float4*)&fjt[4] = *(const float4*)&FjS[lt*32 + tq*8 + 4];

        uint32_t pu[2][8];
#pragma unroll
        for (int m = 0; m < 2; m++) {
#pragma unroll
            for (int t = 0; t < 8; t++) {
                float p = fmaxf(Eir[m]*ejt[t], Fir[m]*fjt[t]);
                p = (mb[m] & (1u << (4*t))) ? p : 0.f;
                const uint32_t pb = __float_as_uint(p) & 0xffffe000u;  // tf32 trunc
                lden[m] += __uint_as_float(pb);                        // consistent
                pu[m][t] = pb;
            }
        }

        // ---- phase B: 16 x m16n8k8 tf32 mma from shared tile
#pragma unroll
        for (int ksi = 0; ksi < 4; ksi++) {
            const float* h0 = &hs[buf][(ksi*8 + tq)*40 + qid];
            const float* h1 = h0 + 4*40;
#pragma unroll
            for (int nt = 0; nt < 4; nt++) {
                const uint32_t b0 = __float_as_uint(h0[nt*8]);
                const uint32_t b1 = __float_as_uint(h1[nt*8]);
                MMA_TF32(acc[nt][0], acc[nt][1], acc[nt][2], acc[nt][3],
                         pu[0][2*ksi], pu[1][2*ksi],
                         pu[0][2*ksi+1], pu[1][2*ksi+1],
                         b0, b1);
            }
        }
        // stage next tile into other buffer; single barrier per iteration
        if (lt < 31)
            *(float4*)&hs[1 - buf][sr] = r0;
        __syncthreads();
    }

    // ---- finish denominators and write normalized output
#pragma unroll
    for (int m = 0; m < 2; m++) {
        lden[m] += __shfl_xor_sync(0xffffffffu, lden[m], 1);
        lden[m] += __shfl_xor_sync(0xffffffffu, lden[m], 2);
        lden[m] = 1.f / lden[m];
    }
#pragma unroll
    for (int half = 0; half < 2; half++) {
        const int grow = i0 + w*16 + qid + 8*half;
        const float rl = lden[half];
        float* orow = out + (bN + grow)*HD + hh*32 + tq*2;
#pragma unroll
        for (int nt = 0; nt < 4; nt++) {
            float2 v = { acc[nt][half*2 + 0]*rl, acc[nt][half*2 + 1]*rl };
            *(float2*)(orow + nt*8) = v;
        }
    }
}

// ---------------------------------------------------------------------------
extern "C" void kernel_launch(void* const* d_in, const int* in_sizes, int n_in,
                              void* d_out, int out_size) {
    const float* x = nullptr; const int* adj = nullptr;
    const float* W = nullptr; const float* bias = nullptr; const float* a = nullptr;
    for (int i = 0; i < n_in; i++) {
        switch (in_sizes[i]) {
            case Bx*Nn*DINc: x    = (const float*)d_in[i]; break;
            case Bx*Nn*Nn:   adj  = (const int*)  d_in[i]; break;
            case DINc*HD:    W    = (const float*)d_in[i]; break;
            case HD:         bias = (const float*)d_in[i]; break;
            case 2*Dd:       a    = (const float*)d_in[i]; break;
        }
    }
    k_gemm<<<BN/32, 256>>>(x, W, bias, a, adj);
    k_attn<<<dim3(8, Hh, Bx), 256>>>((float*)d_out);
}

// round 17
// speedup vs baseline: 1.0657x; 1.0657x over previous
#include <cuda_runtime.h>
#include <cuda_bf16.h>
#include <cstdint>

#define Bx   16
#define Nn   1024
#define DINc 128
#define Hh   4
#define Dd   32
#define HD   128
#define BN   (Bx*Nn)
#define LOG2E 1.4426950408889634f

// ---------------------------------------------------------------------------
// Scratch (device globals — no allocation allowed in kernel_launch)
// ---------------------------------------------------------------------------
__device__ float    g_hT[(size_t)Bx*Hh*Nn*Dd];   // 8.4 MB tf32-rounded, [b][hh][j][d]
__device__ float    g_Ei[(size_t)Hh*BN];         // exp2(ei)      [hh][row]
__device__ float    g_Fi[(size_t)Hh*BN];         // exp2(0.2 ei)
__device__ float    g_Ej[(size_t)Hh*BN];         // PERMUTED within 32-groups
__device__ float    g_Fj[(size_t)Hh*BN];         // (j = tq+4t -> pos = tq*8+t)
__device__ unsigned g_am[(size_t)32*BN];         // [jt][row] packed adjacency bits

__device__ __forceinline__ float tf32r(float x) {
    uint32_t u; asm("cvt.rna.tf32.f32 %0, %1;" : "=r"(u) : "f"(x));
    return __uint_as_float(u);
}
__device__ __forceinline__ float ex2(float x) {
    float p; asm("ex2.approx.ftz.f32 %0, %1;" : "=f"(p) : "f"(x));
    return p;
}
__device__ __forceinline__ uint32_t smem_u32(const void* p) {
    uint32_t a;
    asm("{ .reg .u64 t; cvta.to.shared.u64 t, %1; cvt.u32.u64 %0, t; }" : "=r"(a) : "l"(p));
    return a;
}

#define MMA_TF32(c0,c1,c2,c3, A0,A1,A2,A3, B0,B1) \
    asm("mma.sync.aligned.m16n8k8.row.col.f32.tf32.tf32.f32 " \
        "{%0,%1,%2,%3}, {%4,%5,%6,%7}, {%8,%9}, {%0,%1,%2,%3};" \
        : "+f"(c0), "+f"(c1), "+f"(c2), "+f"(c3) \
        : "r"(A0), "r"(A1), "r"(A2), "r"(A3), "r"(B0), "r"(B1))

// ---------------------------------------------------------------------------
// Kernel 1 (fused): h = x@W + b via 3xTF32 mma.sync  ->  g_hT,
// edge logits from accumulator fragments -> g_Ei/Fi and PERMUTED g_Ej/Fj,
// adjacency bit-packing -> g_am. L2 prefetch of adj before the mainloop.
// ---------------------------------------------------------------------------
__global__ void __launch_bounds__(256, 2) k_gemm(const float* __restrict__ x,
                                                 const float* __restrict__ W,
                                                 const float* __restrict__ bias,
                                                 const float* __restrict__ a,
                                                 const int* __restrict__ adj) {
    __shared__ __align__(16) float xs[32*132];
    __shared__ float as[64];
    const int tid  = threadIdx.x;
    const int lane = tid & 31;
    const int w    = tid >> 5;
    const int qid  = lane >> 2;
    const int tq   = lane & 3;
    const int m0   = (w & 1) * 16;
    const int hh   = w >> 1;
    const int n0   = hh * 32;
    const size_t row0 = (size_t)blockIdx.x * 32;

    for (int i = tid; i < 32*32; i += 256) {
        const int r = i >> 5, c4 = i & 31;
        float4 v = ((const float4*)(x + (row0 + r)*DINc))[c4];
        *(float4*)&xs[r*132 + c4*4] = v;
    }
    if (tid < 64) as[tid] = a[tid];

    // L2 prefetch of this block's 128 KB adj slice (1024 lines, 4/thread)
    {
        const char* abase = (const char*)(adj + row0*Nn);
#pragma unroll
        for (int q = 0; q < 4; q++)
            asm volatile("prefetch.global.L2 [%0];" :: "l"(abase + (size_t)(tid + q*256)*128));
    }
    __syncthreads();

    float acc[4][4];
#pragma unroll
    for (int nt = 0; nt < 4; nt++)
#pragma unroll
        for (int k = 0; k < 4; k++) acc[nt][k] = 0.f;

#pragma unroll
    for (int ks = 0; ks < 16; ks++) {
        const int k0 = ks*8;
        float wv0[4], wv1[4];
        const float* Wk = W + (size_t)(k0 + tq)*HD + n0 + qid;
#pragma unroll
        for (int nt = 0; nt < 4; nt++) wv0[nt] = __ldg(Wk + nt*8);
#pragma unroll
        for (int nt = 0; nt < 4; nt++) wv1[nt] = __ldg(Wk + 4*HD + nt*8);

        const float av0 = xs[(m0+qid  )*132 + k0 + tq];
        const float av1 = xs[(m0+qid+8)*132 + k0 + tq];
        const float av2 = xs[(m0+qid  )*132 + k0 + tq + 4];
        const float av3 = xs[(m0+qid+8)*132 + k0 + tq + 4];
        const float ah0 = tf32r(av0), ah1 = tf32r(av1), ah2 = tf32r(av2), ah3 = tf32r(av3);
        const uint32_t Ah0 = __float_as_uint(ah0), Ah1 = __float_as_uint(ah1);
        const uint32_t Ah2 = __float_as_uint(ah2), Ah3 = __float_as_uint(ah3);
        const uint32_t Al0 = __float_as_uint(av0 - ah0), Al1 = __float_as_uint(av1 - ah1);
        const uint32_t Al2 = __float_as_uint(av2 - ah2), Al3 = __float_as_uint(av3 - ah3);

#pragma unroll
        for (int nt = 0; nt < 4; nt++) {
            const float bh0 = tf32r(wv0[nt]), bh1 = tf32r(wv1[nt]);
            const uint32_t Bh0 = __float_as_uint(bh0), Bh1 = __float_as_uint(bh1);
            const uint32_t Bl0 = __float_as_uint(wv0[nt] - bh0);
            const uint32_t Bl1 = __float_as_uint(wv1[nt] - bh1);
            MMA_TF32(acc[nt][0], acc[nt][1], acc[nt][2], acc[nt][3],
                     Ah0, Ah1, Ah2, Ah3, Bl0, Bl1);
            MMA_TF32(acc[nt][0], acc[nt][1], acc[nt][2], acc[nt][3],
                     Al0, Al1, Al2, Al3, Bh0, Bh1);
            MMA_TF32(acc[nt][0], acc[nt][1], acc[nt][2], acc[nt][3],
                     Ah0, Ah1, Ah2, Ah3, Bh0, Bh1);
        }
    }

    const int b  = (int)(row0 >> 10);
    const int jt = (int)((row0 >> 5) & 31);
    float* htb = g_hT + (((size_t)b*Hh + hh) << 15) + ((size_t)jt*32 << 5);

    float si0 = 0.f, si1 = 0.f, sj0 = 0.f, sj1 = 0.f;
#pragma unroll
    for (int nt = 0; nt < 4; nt++) {
        const int d0 = nt*8 + 2*tq;
        const float bc0 = __ldg(&bias[n0 + d0]), bc1 = __ldg(&bias[n0 + d0 + 1]);
        const float h00 = acc[nt][0] + bc0, h01 = acc[nt][1] + bc1;
        const float h10 = acc[nt][2] + bc0, h11 = acc[nt][3] + bc1;
        const float ai0 = as[d0], ai1 = as[d0 + 1];
        const float aj0 = as[32 + d0], aj1 = as[32 + d0 + 1];
        si0 = fmaf(h00, ai0, fmaf(h01, ai1, si0));
        si1 = fmaf(h10, ai0, fmaf(h11, ai1, si1));
        sj0 = fmaf(h00, aj0, fmaf(h01, aj1, sj0));
        sj1 = fmaf(h10, aj0, fmaf(h11, aj1, sj1));
        float2 v0 = { tf32r(h00), tf32r(h01) };
        float2 v1 = { tf32r(h10), tf32r(h11) };
        *(float2*)(htb + (size_t)(m0 + qid    )*32 + d0) = v0;
        *(float2*)(htb + (size_t)(m0 + qid + 8)*32 + d0) = v1;
    }
#pragma unroll
    for (int o = 1; o <= 2; o <<= 1) {
        si0 += __shfl_xor_sync(0xffffffffu, si0, o);
        si1 += __shfl_xor_sync(0xffffffffu, si1, o);
        sj0 += __shfl_xor_sync(0xffffffffu, sj0, o);
        sj1 += __shfl_xor_sync(0xffffffffu, sj1, o);
    }
    if (tq == 0) {
        const size_t base = (size_t)hh*BN + row0;
        const int r1 = m0 + qid, r2 = m0 + qid + 8;
        const int p1 = ((r1 & 3) << 3) | (r1 >> 2);   // permuted j positions
        const int p2 = ((r2 & 3) << 3) | (r2 >> 2);
        const float e0 = si0*LOG2E, e1 = si1*LOG2E;
        const float f0 = sj0*LOG2E, f1 = sj1*LOG2E;
        g_Ei[base + r1] = ex2(e0);      g_Ei[base + r2] = ex2(e1);
        g_Fi[base + r1] = ex2(0.2f*e0); g_Fi[base + r2] = ex2(0.2f*e1);
        g_Ej[base + p1] = ex2(f0);      g_Ej[base + p2] = ex2(f1);
        g_Fj[base + p1] = ex2(0.2f*f0); g_Fj[base + p2] = ex2(0.2f*f1);
    }

    // ---- adjacency pack: batched loads (L2 hits), shfl-or reduction
#pragma unroll
    for (int rr = 0; rr < 4; rr++) {
        const size_t row = row0 + w*4 + rr;
        const int4* arow = (const int4*)(adj + row*Nn);
        int4 v[8];
#pragma unroll
        for (int c = 0; c < 8; c++) v[c] = __ldg(&arow[c*32 + lane]);
#pragma unroll
        for (int c = 0; c < 8; c++) {
            unsigned nib = (unsigned)(v[c].x > 0) | ((unsigned)(v[c].y > 0) << 1)
                         | ((unsigned)(v[c].z > 0) << 2) | ((unsigned)(v[c].w > 0) << 3);
            nib <<= (lane & 7)*4;
            nib |= __shfl_xor_sync(0xffffffffu, nib, 1);
            nib |= __shfl_xor_sync(0xffffffffu, nib, 2);
            nib |= __shfl_xor_sync(0xffffffffu, nib, 4);
            if ((lane & 7) == 0)
                g_am[(size_t)(c*4 + (lane >> 3))*BN + row] = nib;
        }
    }
}

// ---------------------------------------------------------------------------
// Kernel 2: flash attention, mma.sync tf32, fully sync-free warps.
// Grid (8, Hh, Bx), 128 thr = 4 warps; warp owns 32 i-rows independently.
// cp.async double-buffered per-warp h tile; denominator via all-ones column
// (5th n-block MMA) -> automatic num/den consistency, no shfl epilogue.
// Ej/Fj read directly from gmem (pre-permuted by k_gemm). Zero __syncthreads.
// ---------------------------------------------------------------------------
__global__ void __launch_bounds__(128, 4) k_attn(float* __restrict__ out) {
    __shared__ __align__(16) float hsw[4][2][32*40];   // 40 KB per-warp dbl buffers

    const int tid  = threadIdx.x;
    const int lane = tid & 31;
    const int w    = tid >> 5;
    const int qid  = lane >> 2;            // 0..7
    const int tq   = lane & 3;             // 0..3
    const int hh   = blockIdx.y;
    const int b    = blockIdx.z;
    const int i0   = blockIdx.x * 128;
    const size_t bN = (size_t)b * Nn;

    float Eir[4], Fir[4];
#pragma unroll
    for (int m = 0; m < 4; m++) {
        const size_t o = (size_t)hh*BN + bN + i0 + w*32 + qid + 8*m;
        Eir[m] = __ldg(&g_Ei[o]);
        Fir[m] = __ldg(&g_Fi[o]);
    }

    float acc[2][5][4];
#pragma unroll
    for (int mt = 0; mt < 2; mt++)
#pragma unroll
        for (int nt = 0; nt < 5; nt++)
#pragma unroll
            for (int k = 0; k < 4; k++) acc[mt][nt][k] = 0.f;

    const float* htsrc = g_hT + (((size_t)b*Hh + hh) << 15);
    const unsigned* amp = g_am + bN + i0 + w*32 + qid;
    const float* ejp = g_Ej + (size_t)hh*BN + bN;
    const float* fjp = g_Fj + (size_t)hh*BN + bN;

    // per-lane cp.async chunk geometry: chunk i covers row i>>3, cols (i&7)*4
    uint32_t dstb[2];
    dstb[0] = smem_u32(&hsw[w][0][0]);
    dstb[1] = smem_u32(&hsw[w][1][0]);
    uint32_t doff[8];
#pragma unroll
    for (int it = 0; it < 8; it++) {
        const int i = it*32 + lane;
        doff[it] = (uint32_t)(((i >> 3)*40 + (i & 7)*4) * 4);
    }

    // prologue: tile 0 -> buf 0
#pragma unroll
    for (int it = 0; it < 8; it++)
        asm volatile("cp.async.ca.shared.global [%0], [%1], 16;"
                     :: "r"(dstb[0] + doff[it]), "l"(htsrc + (it*32 + lane)*4) : "memory");
    asm volatile("cp.async.commit_group;" ::: "memory");

    const uint32_t ONE = 0x3F800000u;

    for (int jt = 0; jt < 32; jt++) {
        const int buf = jt & 1;
        // issue next tile's cp.async early (targets the other buffer)
        if (jt < 31) {
            const float* src = htsrc + (size_t)(jt + 1)*1024;
#pragma unroll
            for (int it = 0; it < 8; it++)
                asm volatile("cp.async.ca.shared.global [%0], [%1], 16;"
                             :: "r"(dstb[1 - buf] + doff[it]), "l"(src + (it*32 + lane)*4) : "memory");
            asm volatile("cp.async.commit_group;" ::: "memory");
            asm volatile("cp.async.wait_group 1;" ::: "memory");
        } else {
            asm volatile("cp.async.wait_group 0;" ::: "memory");
        }
        __syncwarp();

        // masks
        unsigned mb[4];
#pragma unroll
        for (int m = 0; m < 4; m++)
            mb[m] = __ldg(amp + (size_t)jt*BN + 8*m) >> tq;

        // ---- phase A: P in A-fragment registers (ej/fj direct from gmem)
        float ejt[8], fjt[8];
        *(float4*)&ejt[0] = *(const float4*)(ejp + jt*32 + tq*8);
        *(float4*)&ejt[4] = *(const float4*)(ejp + jt*32 + tq*8 + 4);
        *(float4*)&fjt[0] = *(const float4*)(fjp + jt*32 + tq*8);
        *(float4*)&fjt[4] = *(const float4*)(fjp + jt*32 + tq*8 + 4);

        uint32_t pu[4][8];
#pragma unroll
        for (int m = 0; m < 4; m++) {
#pragma unroll
            for (int t = 0; t < 8; t++) {
                float p = fmaxf(Eir[m]*ejt[t], Fir[m]*fjt[t]);
                p = (mb[m] & (1u << (4*t))) ? p : 0.f;
                pu[m][t] = __float_as_uint(p);   // MMA truncates num & den identically
            }
        }

        // ---- phase B: (4 h-blocks + 1 ones-block) x 4 ks x 2 mt MMAs
        const float* hb = (const float*)&hsw[w][buf][0];
#pragma unroll
        for (int ksi = 0; ksi < 4; ksi++) {
            const float* h0 = &hb[(ksi*8 + tq)*40 + qid];
            const float* h1 = h0 + 4*40;
#pragma unroll
            for (int nt = 0; nt < 4; nt++) {
                const uint32_t b0 = __float_as_uint(h0[nt*8]);
                const uint32_t b1 = __float_as_uint(h1[nt*8]);
#pragma unroll
                for (int mt = 0; mt < 2; mt++) {
                    MMA_TF32(acc[mt][nt][0], acc[mt][nt][1],
                             acc[mt][nt][2], acc[mt][nt][3],
                             pu[2*mt][2*ksi], pu[2*mt+1][2*ksi],
                             pu[2*mt][2*ksi+1], pu[2*mt+1][2*ksi+1],
                             b0, b1);
                }
            }
#pragma unroll
            for (int mt = 0; mt < 2; mt++) {
                MMA_TF32(acc[mt][4][0], acc[mt][4][1],
                         acc[mt][4][2], acc[mt][4][3],
                         pu[2*mt][2*ksi], pu[2*mt+1][2*ksi],
                         pu[2*mt][2*ksi+1], pu[2*mt+1][2*ksi+1],
                         ONE, ONE);
            }
        }
    }

    // ---- write normalized output; denominator = ones-column accumulator
#pragma unroll
    for (int mt = 0; mt < 2; mt++) {
#pragma unroll
        for (int half = 0; half < 2; half++) {
            const int grow = i0 + w*32 + mt*16 + qid + 8*half;
            const float rl = 1.f / acc[mt][4][half*2];
            float* orow = out + (bN + grow)*HD + hh*32 + tq*2;
#pragma unroll
            for (int nt = 0; nt < 4; nt++) {
                float2 v = { acc[mt][nt][half*2 + 0]*rl, acc[mt][nt][half*2 + 1]*rl };
                *(float2*)(orow + nt*8) = v;
            }
        }
    }
}

// ---------------------------------------------------------------------------
extern "C" void kernel_launch(void* const* d_in, const int* in_sizes, int n_in,
                              void* d_out, int out_size) {
    const float* x = nullptr; const int* adj = nullptr;
    const float* W = nullptr; const float* bias = nullptr; const float* a = nullptr;
    for (int i = 0; i < n_in; i++) {
        switch (in_sizes[i]) {
            case Bx*Nn*DINc: x    = (const float*)d_in[i]; break;
            case Bx*Nn*Nn:   adj  = (const int*)  d_in[i]; break;
            case DINc*HD:    W    = (const float*)d_in[i]; break;
            case HD:         bias = (const float*)d_in[i]; break;
            case 2*Dd:       a    = (const float*)d_in[i]; break;
        }
    }
    k_gemm<<<BN/32, 256>>>(x, W, bias, a, adj);
    k_attn<<<dim3(8, Hh, Bx), 128>>>((float*)d_out);
}